// round 3
// baseline (speedup 1.0000x reference)
#include <cuda_runtime.h>
#include <cuda_bf16.h>

// Depthwise conv 31x31, pad 15, stride 1, fp32.
// x: [32, 384, 56, 56], w: [384, 1, 31, 31], bias: [384], out: [32, 384, 56, 56]
//
// One block per (n,c) plane. Input plane staged in smem twice (plain + shifted
// by one float) so both even- and odd-aligned float pairs are 8B-aligned
// LDS.64. Weights staged duplicated as (w,w) u64. Inner loop is pure
// fma.rn.f32x2 (packed fp32 FMA, 2x scalar FFMA throughput on sm_103a).

#define ROWS 86           // 56 + 2*15
#define COLS 86
#define SSTRIDE 100       // row stride in floats; 100 % 32 == 4 -> conflict-free LDS.64
#define NTHREADS 224      // 56 rows * 4 col-groups of 14 outputs

__global__ void __launch_bounds__(NTHREADS, 2)
dwconv31_f32x2_kernel(const float* __restrict__ x,
                      const float* __restrict__ w,
                      const float* __restrict__ bias,
                      float* __restrict__ out)
{
    const int plane = blockIdx.x;          // n*384 + c
    const int ch = plane - (plane / 384) * 384;

    extern __shared__ float sm[];
    float* inA = sm;                                   // ROWS * SSTRIDE
    float* inB = sm + ROWS * SSTRIDE;                  // shifted copy: inB[r][c] = inA[r][c+1]
    unsigned long long* wd =
        (unsigned long long*)(sm + 2 * ROWS * SSTRIDE); // 961 duplicated weight pairs

    const float* xp = x + (long long)plane * (56 * 56);

    // Stage duplicated weights: wd[i] = (w_i, w_i)
    for (int i = threadIdx.x; i < 961; i += NTHREADS) {
        float v = w[ch * 961 + i];
        unsigned long long p;
        asm("mov.b64 %0, {%1, %1};" : "=l"(p) : "f"(v));
        wd[i] = p;
    }

    // Stage padded input plane (zero halo) + shifted copy.
    for (int i = threadIdx.x; i < ROWS * COLS; i += NTHREADS) {
        int r = i / COLS;
        int c = i - r * COLS;
        int gy = r - 15, gx = c - 15;
        float v = 0.0f;
        if ((unsigned)gy < 56u && (unsigned)gx < 56u)
            v = xp[gy * 56 + gx];
        inA[r * SSTRIDE + c] = v;
        if (c > 0)   inB[r * SSTRIDE + c - 1] = v;
        if (c == COLS - 1) inB[r * SSTRIDE + c] = 0.0f;  // inA[r][86] is never read
    }
    __syncthreads();

    const int y  = threadIdx.x >> 2;          // 0..55 output row
    const int xx = (threadIdx.x & 3) * 14;    // 0,14,28,42 output col base

    unsigned long long acc[7];
#pragma unroll
    for (int j = 0; j < 7; ++j) acc[j] = 0ull;

#pragma unroll 1
    for (int dy = 0; dy < 31; ++dy) {
        const unsigned long long* pA =
            (const unsigned long long*)(inA + (y + dy) * SSTRIDE + xx);
        const unsigned long long* pB =
            (const unsigned long long*)(inB + (y + dy) * SSTRIDE + xx);
        const unsigned long long* wrow = wd + dy * 31;

        // even taps: pair k = dx + 2j with dx = 2e  -> aligned pair pA[e+j]
#pragma unroll
        for (int e = 0; e < 16; ++e) {
            unsigned long long w2 = wrow[2 * e];
#pragma unroll
            for (int j = 0; j < 7; ++j)
                asm("fma.rn.f32x2 %0, %1, %2, %0;"
                    : "+l"(acc[j]) : "l"(pA[e + j]), "l"(w2));
        }
        // odd taps: dx = 2o+1 -> shifted pair pB[o+j]
#pragma unroll
        for (int o = 0; o < 15; ++o) {
            unsigned long long w2 = wrow[2 * o + 1];
#pragma unroll
            for (int j = 0; j < 7; ++j)
                asm("fma.rn.f32x2 %0, %1, %2, %0;"
                    : "+l"(acc[j]) : "l"(pB[o + j]), "l"(w2));
        }
    }

    const float b = bias[ch];
    float* op = out + (long long)plane * (56 * 56) + y * 56 + xx;
#pragma unroll
    for (int j = 0; j < 7; ++j) {
        float lo, hi;
        asm("mov.b64 {%0, %1}, %2;" : "=f"(lo), "=f"(hi) : "l"(acc[j]));
        float2 v = make_float2(lo + b, hi + b);
        *reinterpret_cast<float2*>(op + 2 * j) = v;
    }
}

extern "C" void kernel_launch(void* const* d_in, const int* in_sizes, int n_in,
                              void* d_out, int out_size)
{
    const float* x    = (const float*)d_in[0];
    const float* w    = (const float*)d_in[1];
    const float* bias = (const float*)d_in[2];
    float* out = (float*)d_out;

    const int smem_bytes = (2 * ROWS * SSTRIDE) * 4 + 961 * 8;  // 76,488 B

    cudaFuncSetAttribute(dwconv31_f32x2_kernel,
                         cudaFuncAttributeMaxDynamicSharedMemorySize, smem_bytes);

    dim3 grid(32 * 384);
    dim3 block(NTHREADS);
    dwconv31_f32x2_kernel<<<grid, block, smem_bytes>>>(x, w, bias, out);
}